// round 3
// baseline (speedup 1.0000x reference)
#include <cuda_runtime.h>
#include <math.h>

#define BB 256
#define TT 20
#define DD 128
#define HH 256
#define KSZ 256
#define MEMN 20
#define YY 4
#define EPSF 1e-8f
#define NFRM (BB*TT)
#define NBLK 256

// ---------------- device scratch ----------------
__device__ float g_h3[NFRM*512];
__device__ float g_fc1[NFRM*256];
__device__ float g_z[NFRM*DD];
__device__ float g_heads[BB*768];
__device__ float g_h[2*BB*HH];      // ping-pong h state
__device__ float g_cst[BB*HH];
__device__ float g_r[BB*KSZ];
__device__ float g_M[BB*MEMN*KSZ];
__device__ float g_Minv[BB*MEMN];
__device__ float g_Wcat[1024*640];  // rows interleaved (j,gate)
__device__ float g_bias[1024];      // interleaved (j,gate)
__device__ float g_Whead[768*256];
__device__ unsigned g_barctr;

__device__ __forceinline__ float sigmf(float x){ return 1.f/(1.f+expf(-x)); }

// ---------------- fused conv encoder: one frame per block ----------------
#define S_IN 0
#define S_H1 1156
#define S_H2 12676
#define CONV_SMEM_FLOATS 16516

__global__ void __launch_bounds__(256, 3) k_conv(
    const float* __restrict__ x,
    const float* __restrict__ w1, const float* __restrict__ b1,
    const float* __restrict__ w2, const float* __restrict__ b2,
    const float* __restrict__ w3, const float* __restrict__ b3)
{
    extern __shared__ float sm[];
    float* s_in = sm + S_IN;
    float* s_h1 = sm + S_H1;
    float* s_h2 = sm + S_H2;
    const int f   = blockIdx.x;
    const int tid = threadIdx.x;

    for (int i = tid; i < CONV_SMEM_FLOATS; i += 256) sm[i] = 0.f;
    __syncthreads();
    for (int i = tid; i < 1024; i += 256) {
        int iy = i >> 5, ix = i & 31;
        s_in[(iy+1)*34 + ix + 1] = x[f*1024 + i];
    }
    __syncthreads();

    // ---- conv1: 1->32ch, 32x32 -> 16x16 ----
    for (int p = tid; p < 32*16; p += 256) {
        int oc = p >> 4, oy = p & 15;
        float bias = __ldg(b1 + oc);
        float acc[16];
        #pragma unroll
        for (int ox = 0; ox < 16; ox++) acc[ox] = bias;
        #pragma unroll
        for (int kh = 0; kh < 4; kh++) {
            const float* row = s_in + (2*oy+kh)*34;
            const float4 w = __ldg((const float4*)(w1 + oc*16 + kh*4));
            #pragma unroll
            for (int ox = 0; ox < 16; ox++) {
                acc[ox] += row[2*ox]*w.x + row[2*ox+1]*w.y
                         + row[2*ox+2]*w.z + row[2*ox+3]*w.w;
            }
        }
        float* dst = s_h1 + oc*360 + (oy+1)*20 + 1;
        #pragma unroll
        for (int ox = 0; ox < 16; ox++) dst[ox] = fmaxf(acc[ox], 0.f);
    }
    __syncthreads();

    // ---- conv2: 32->32ch, 16x16 -> 8x8; thread = (oc pair, oy, ox half) ----
    {
        int ocp = tid >> 4;          // 0..15
        int oy  = (tid >> 1) & 7;    // 0..7
        int oxh = tid & 1;           // 0..1
        int oc0 = ocp*2, oc1 = oc0 + 1;
        float bv0 = __ldg(b2 + oc0), bv1 = __ldg(b2 + oc1);
        float acc0[4] = {bv0, bv0, bv0, bv0};
        float acc1[4] = {bv1, bv1, bv1, bv1};
        for (int ic = 0; ic < 32; ic++) {
            const float* chan = s_h1 + ic*360;
            #pragma unroll
            for (int kh = 0; kh < 4; kh++) {
                const float* row = chan + (2*oy+kh)*20 + 8*oxh;
                float4 ra = *(const float4*)(row);
                float4 rb = *(const float4*)(row+4);
                float4 rc = *(const float4*)(row+8);
                float r[12] = {ra.x,ra.y,ra.z,ra.w, rb.x,rb.y,rb.z,rb.w,
                               rc.x,rc.y,rc.z,rc.w};
                const float4 w0 = __ldg((const float4*)(w2 + oc0*512 + ic*16 + kh*4));
                const float4 w1v= __ldg((const float4*)(w2 + oc1*512 + ic*16 + kh*4));
                #pragma unroll
                for (int ox = 0; ox < 4; ox++) {
                    acc0[ox] += r[2*ox]*w0.x + r[2*ox+1]*w0.y + r[2*ox+2]*w0.z + r[2*ox+3]*w0.w;
                    acc1[ox] += r[2*ox]*w1v.x + r[2*ox+1]*w1v.y + r[2*ox+2]*w1v.z + r[2*ox+3]*w1v.w;
                }
            }
        }
        float* d0 = s_h2 + oc0*120 + (oy+1)*12 + 1 + 4*oxh;
        float* d1 = s_h2 + oc1*120 + (oy+1)*12 + 1 + 4*oxh;
        #pragma unroll
        for (int ox = 0; ox < 4; ox++) {
            d0[ox] = fmaxf(acc0[ox], 0.f);
            d1[ox] = fmaxf(acc1[ox], 0.f);
        }
    }
    __syncthreads();

    // ---- conv3: 32->32ch, 8x8 -> 4x4 ----
    {
        int oc = tid >> 3, oy = (tid >> 1) & 3, q = tid & 1;
        float bias = __ldg(b3 + oc);
        float acc0 = bias, acc1 = bias;
        for (int ic = 0; ic < 32; ic++) {
            const float* chan = s_h2 + ic*120;
            #pragma unroll
            for (int kh = 0; kh < 4; kh++) {
                const float* row = chan + (2*oy+kh)*12 + 4*q;
                float4 a = *(const float4*)(row);
                float4 b = *(const float4*)(row+4);
                const float4 w = __ldg((const float4*)(w3 + oc*512 + ic*16 + kh*4));
                acc0 += a.x*w.x + a.y*w.y + a.z*w.z + a.w*w.w;
                acc1 += a.z*w.x + a.w*w.y + b.x*w.z + b.y*w.w;
            }
        }
        int base = f*512 + oc*16 + oy*4 + 2*q;
        g_h3[base]   = fmaxf(acc0, 0.f);
        g_h3[base+1] = fmaxf(acc1, 0.f);
    }
}

// ---------------- fp32 GEMM (fc layers): C = relu(A @ W^T + bias) ----------------
__global__ void __launch_bounds__(256) k_gemm(
    const float* __restrict__ A, int lda,
    const float* __restrict__ W, int ldw,
    const float* __restrict__ bias,
    float* __restrict__ C, int ldc, int K)
{
    __shared__ float sA[2][16][68];
    __shared__ float sW[2][16][68];
    int tid = threadIdx.x;
    int tx = tid & 15, ty = tid >> 4;
    int lr = tid >> 2;
    int lk = (tid & 3) << 2;
    const float* Ab = A + (blockIdx.y*64 + lr)*lda + lk;
    const float* Wb = W + (blockIdx.x*64 + lr)*ldw + lk;

    float acc[4][4];
    #pragma unroll
    for (int i = 0; i < 4; i++)
        #pragma unroll
        for (int j = 0; j < 4; j++) acc[i][j] = 0.f;

    int nk = K >> 4;
    float4 a4 = *(const float4*)(Ab);
    float4 w4 = *(const float4*)(Wb);
    sA[0][lk+0][lr] = a4.x; sA[0][lk+1][lr] = a4.y; sA[0][lk+2][lr] = a4.z; sA[0][lk+3][lr] = a4.w;
    sW[0][lk+0][lr] = w4.x; sW[0][lk+1][lr] = w4.y; sW[0][lk+2][lr] = w4.z; sW[0][lk+3][lr] = w4.w;
    __syncthreads();

    for (int kb = 0; kb < nk; kb++) {
        int s = kb & 1;
        float4 na, nw;
        if (kb + 1 < nk) {
            na = *(const float4*)(Ab + ((kb+1) << 4));
            nw = *(const float4*)(Wb + ((kb+1) << 4));
        }
        #pragma unroll
        for (int kk = 0; kk < 16; kk++) {
            float4 av = *(const float4*)&sA[s][kk][ty<<2];
            float4 wv = *(const float4*)&sW[s][kk][tx<<2];
            float a[4] = {av.x, av.y, av.z, av.w};
            float w[4] = {wv.x, wv.y, wv.z, wv.w};
            #pragma unroll
            for (int i = 0; i < 4; i++)
                #pragma unroll
                for (int j = 0; j < 4; j++) acc[i][j] += a[i]*w[j];
        }
        if (kb + 1 < nk) {
            int d = s ^ 1;
            sA[d][lk+0][lr] = na.x; sA[d][lk+1][lr] = na.y; sA[d][lk+2][lr] = na.z; sA[d][lk+3][lr] = na.w;
            sW[d][lk+0][lr] = nw.x; sW[d][lk+1][lr] = nw.y; sW[d][lk+2][lr] = nw.z; sW[d][lk+3][lr] = nw.w;
            __syncthreads();
        }
    }
    int rb = blockIdx.y*64 + (ty<<2);
    int cb = blockIdx.x*64 + (tx<<2);
    #pragma unroll
    for (int i = 0; i < 4; i++)
        #pragma unroll
        for (int j = 0; j < 4; j++)
            C[(rb+i)*ldc + cb + j] = fmaxf(acc[i][j] + bias[cb+j], 0.f);
}

// ---------------- context norm over time ----------------
__global__ void k_ctxnorm(const float* __restrict__ gamma, const float* __restrict__ beta)
{
    int b = blockIdx.x, d = threadIdx.x;
    float v[TT];
    float s = 0.f, s2 = 0.f;
    #pragma unroll
    for (int t = 0; t < TT; t++) {
        v[t] = g_z[(b*TT+t)*DD + d];
        s += v[t]; s2 += v[t]*v[t];
    }
    float mu  = s / TT;
    float var = (s2 - TT*mu*mu) / (TT - 1);
    float inv = 1.f / sqrtf(var + EPSF);
    float ga = gamma[d], be = beta[d];
    #pragma unroll
    for (int t = 0; t < TT; t++)
        g_z[(b*TT+t)*DD + d] = (v[t] - mu)*inv*ga + be;
}

// ---------------- setup: states, reordered weights, out zero, barrier reset ----------------
__global__ void k_setup(const float* __restrict__ mem0,
                        const float* __restrict__ wi, const float* __restrict__ wh,
                        const float* __restrict__ lb,
                        const float* __restrict__ wk, const float* __restrict__ wwk,
                        const float* __restrict__ wv,
                        float* __restrict__ out, int out_size)
{
    int i = blockIdx.x*256 + threadIdx.x;
    if (i == 0) g_barctr = 0u;
    if (i < BB*MEMN*KSZ) g_M[i] = mem0[i % (MEMN*KSZ)];
    if (i < 1024*640) {
        int rowp = i / 640, c = i - rowp*640;
        int j = rowp >> 2, gt = rowp & 3;
        int orig = gt*256 + j;
        g_Wcat[i] = (c < 384) ? wi[orig*384 + c] : wh[orig*256 + (c-384)];
    }
    if (i < 1024) {
        int j = i >> 2, gt = i & 3;
        g_bias[i] = lb[gt*256 + j];
    }
    if (i < 768*256) {
        int n = i >> 8;
        g_Whead[i] = (n < 256) ? wk[i] : ((n < 512) ? wwk[i - 256*256] : wv[i - 512*256]);
    }
    if (i < 2*BB*HH) g_h[i] = 0.f;
    if (i < BB*HH) g_cst[i] = 0.f;
    if (i < BB*KSZ) g_r[i] = 0.f;
    if (i < out_size) out[i] = 0.f;
}

// ---------------- grid barrier (all NBLK blocks resident by construction) ----------------
__device__ __forceinline__ void gridbar(unsigned target)
{
    __syncthreads();
    if (threadIdx.x == 0) {
        __threadfence();
        atomicAdd(&g_barctr, 1u);
        unsigned v;
        do {
            asm volatile("ld.global.acquire.gpu.u32 %0, [%1];" : "=r"(v) : "l"(&g_barctr));
            if (v < target) __nanosleep(64);
        } while (v < target);
    }
    __syncthreads();
}

__device__ __forceinline__ float4 ldA_gates(const float* __restrict__ hcur,
                                            int b, int c, int t)
{
    if (c < DD)           return *(const float4*)(g_z + (b*TT + t)*DD + c);
    else if (c < DD+KSZ)  return *(const float4*)(g_r + b*KSZ + (c - DD));
    else                  return *(const float4*)(hcur + b*HH + (c - DD - KSZ));
}

// ---------------- persistent scan: whole 20-step recurrence, one launch ----------------
__global__ void __launch_bounds__(256, 2) k_scan(
    const float* __restrict__ wo, const float* __restrict__ wob,
    float* __restrict__ out, int out_size)
{
    __shared__ float sA[2][16][68];
    __shared__ float sW[2][16][68];
    __shared__ float s_kr[256], s_kw[256], s_rnew[256];
    __shared__ float s_simr[MEMN], s_simw[MEMN];
    __shared__ float s_wr[4], s_ws[4];
    __shared__ int   s_ir[4], s_iw[4];
    __shared__ float s_red[16];
    __shared__ float s_nrm[2];
    __shared__ float s_y[4];

    const int blk = blockIdx.x;
    const int tid = threadIdx.x;
    const int lane = tid & 31, wid = tid >> 5;
    const int tx = tid & 15, ty = tid >> 4;
    const int lr = tid >> 2, lk = (tid & 3) << 2;
    unsigned bt = 0;

    for (int t = 0; t < TT; t++) {
        const float* hcur = g_h + (t & 1)*BB*HH;
        float*       hnxt = g_h + ((t + 1) & 1)*BB*HH;

        // ======== phase 1: gates GEMM (blocks 0..63) + fused LSTM epilogue;
        // ======== blocks 64..255: memory-row inverse norms
        if (blk < 64) {
            int mt = blk & 3, nt = blk >> 2;
            int rowA = mt*64 + lr;
            const float* Wb = g_Wcat + (nt*64 + lr)*640 + lk;

            float acc[4][4];
            #pragma unroll
            for (int i = 0; i < 4; i++)
                #pragma unroll
                for (int j = 0; j < 4; j++) acc[i][j] = 0.f;

            float4 a4 = ldA_gates(hcur, rowA, lk, t);
            float4 w4 = *(const float4*)(Wb);
            sA[0][lk+0][lr] = a4.x; sA[0][lk+1][lr] = a4.y; sA[0][lk+2][lr] = a4.z; sA[0][lk+3][lr] = a4.w;
            sW[0][lk+0][lr] = w4.x; sW[0][lk+1][lr] = w4.y; sW[0][lk+2][lr] = w4.z; sW[0][lk+3][lr] = w4.w;
            __syncthreads();

            #pragma unroll 1
            for (int kb = 0; kb < 40; kb++) {
                int s = kb & 1;
                float4 na, nw;
                if (kb + 1 < 40) {
                    na = ldA_gates(hcur, rowA, ((kb+1) << 4) + lk, t);
                    nw = *(const float4*)(Wb + ((kb+1) << 4));
                }
                #pragma unroll
                for (int kk = 0; kk < 16; kk++) {
                    float4 av = *(const float4*)&sA[s][kk][ty<<2];
                    float4 wv = *(const float4*)&sW[s][kk][tx<<2];
                    float a[4] = {av.x, av.y, av.z, av.w};
                    float w[4] = {wv.x, wv.y, wv.z, wv.w};
                    #pragma unroll
                    for (int i = 0; i < 4; i++)
                        #pragma unroll
                        for (int j = 0; j < 4; j++) acc[i][j] += a[i]*w[j];
                }
                if (kb + 1 < 40) {
                    int d = s ^ 1;
                    sA[d][lk+0][lr] = na.x; sA[d][lk+1][lr] = na.y; sA[d][lk+2][lr] = na.z; sA[d][lk+3][lr] = na.w;
                    sW[d][lk+0][lr] = nw.x; sW[d][lk+1][lr] = nw.y; sW[d][lk+2][lr] = nw.z; sW[d][lk+3][lr] = nw.w;
                    __syncthreads();
                }
            }
            // fused LSTM epilogue: thread's 4 N-cols are the 4 gates of j
            int j = nt*16 + tx;
            float4 bb = *(const float4*)(g_bias + j*4);
            #pragma unroll
            for (int i = 0; i < 4; i++) {
                int b = mt*64 + (ty<<2) + i;
                float ig = acc[i][0] + bb.x;
                float fg = acc[i][1] + bb.y;
                float gg = acc[i][2] + bb.z;
                float og = acc[i][3] + bb.w;
                float cn = sigmf(fg)*g_cst[b*HH + j] + sigmf(ig)*tanhf(gg);
                float hn = sigmf(og)*tanhf(cn);
                g_cst[b*HH + j] = cn;
                hnxt[b*HH + j]  = hn;
            }
        } else {
            // inverse norms of all memory rows (M stable during this phase)
            int w = (blk - 64)*8 + wid;
            for (int row = w; row < BB*MEMN; row += 192*8) {
                const float* Mr = g_M + row*KSZ;
                float nn = 0.f;
                #pragma unroll
                for (int d0 = 0; d0 < KSZ; d0 += 32) {
                    float m = Mr[d0 + lane];
                    nn += m*m;
                }
                #pragma unroll
                for (int o = 16; o > 0; o >>= 1) nn += __shfl_xor_sync(0xffffffffu, nn, o);
                if (lane == 0) g_Minv[row] = 1.f / (sqrtf(nn) + EPSF);
            }
        }
        bt += NBLK; gridbar(bt);

        // ======== phase 2: heads GEMM (blocks 0..47), tanh fused for v slice
        if (blk < 48) {
            int mt = blk & 3, nt = blk >> 2;   // nt 0..11
            const float* Ab = hnxt + (mt*64 + lr)*HH + lk;
            const float* Wb = g_Whead + (nt*64 + lr)*256 + lk;

            float acc[4][4];
            #pragma unroll
            for (int i = 0; i < 4; i++)
                #pragma unroll
                for (int j = 0; j < 4; j++) acc[i][j] = 0.f;

            float4 a4 = *(const float4*)(Ab);
            float4 w4 = *(const float4*)(Wb);
            sA[0][lk+0][lr] = a4.x; sA[0][lk+1][lr] = a4.y; sA[0][lk+2][lr] = a4.z; sA[0][lk+3][lr] = a4.w;
            sW[0][lk+0][lr] = w4.x; sW[0][lk+1][lr] = w4.y; sW[0][lk+2][lr] = w4.z; sW[0][lk+3][lr] = w4.w;
            __syncthreads();

            #pragma unroll 1
            for (int kb = 0; kb < 16; kb++) {
                int s = kb & 1;
                float4 na, nw;
                if (kb + 1 < 16) {
                    na = *(const float4*)(Ab + ((kb+1) << 4));
                    nw = *(const float4*)(Wb + ((kb+1) << 4));
                }
                #pragma unroll
                for (int kk = 0; kk < 16; kk++) {
                    float4 av = *(const float4*)&sA[s][kk][ty<<2];
                    float4 wv = *(const float4*)&sW[s][kk][tx<<2];
                    float a[4] = {av.x, av.y, av.z, av.w};
                    float w[4] = {wv.x, wv.y, wv.z, wv.w};
                    #pragma unroll
                    for (int i = 0; i < 4; i++)
                        #pragma unroll
                        for (int j = 0; j < 4; j++) acc[i][j] += a[i]*w[j];
                }
                if (kb + 1 < 16) {
                    int d = s ^ 1;
                    sA[d][lk+0][lr] = na.x; sA[d][lk+1][lr] = na.y; sA[d][lk+2][lr] = na.z; sA[d][lk+3][lr] = na.w;
                    sW[d][lk+0][lr] = nw.x; sW[d][lk+1][lr] = nw.y; sW[d][lk+2][lr] = nw.z; sW[d][lk+3][lr] = nw.w;
                    __syncthreads();
                }
            }
            int rb = mt*64 + (ty<<2);
            int cb = nt*64 + (tx<<2);
            #pragma unroll
            for (int i = 0; i < 4; i++)
                #pragma unroll
                for (int j = 0; j < 4; j++) {
                    float v = acc[i][j];
                    if (cb + j >= 512) v = tanhf(v);
                    g_heads[(rb+i)*768 + cb + j] = v;
                }
        }
        bt += NBLK; gridbar(bt);

        // ======== phase 3: memory read/write per batch (block = batch)
        {
            int b = blk;
            const float* hd = g_heads + b*768;
            float kr = hd[tid];
            float kw = hd[256 + tid];
            float vv = hd[512 + tid];   // already tanh'd
            s_kr[tid] = kr;
            s_kw[tid] = kw;

            float pr = kr*kr, pw = kw*kw;
            #pragma unroll
            for (int o = 16; o > 0; o >>= 1) {
                pr += __shfl_xor_sync(0xffffffffu, pr, o);
                pw += __shfl_xor_sync(0xffffffffu, pw, o);
            }
            if (lane == 0) { s_red[wid] = pr; s_red[8 + wid] = pw; }
            __syncthreads();
            if (tid == 0) {
                float sr = 0.f, sw = 0.f;
                #pragma unroll
                for (int w = 0; w < 8; w++) { sr += s_red[w]; sw += s_red[8 + w]; }
                s_nrm[0] = 1.f / (sqrtf(sr) + EPSF);
                s_nrm[1] = 1.f / (sqrtf(sw) + EPSF);
            }
            __syncthreads();

            for (int n = wid; n < MEMN; n += 8) {
                const float* Mr = g_M + (b*MEMN + n)*KSZ;
                float dr = 0.f, dw = 0.f;
                #pragma unroll
                for (int d0 = 0; d0 < KSZ; d0 += 32) {
                    float m = Mr[d0 + lane];
                    dr += s_kr[d0 + lane]*m;
                    dw += s_kw[d0 + lane]*m;
                }
                #pragma unroll
                for (int o = 16; o > 0; o >>= 1) {
                    dr += __shfl_xor_sync(0xffffffffu, dr, o);
                    dw += __shfl_xor_sync(0xffffffffu, dw, o);
                }
                if (lane == 0) {
                    float mi = g_Minv[b*MEMN + n];
                    s_simr[n] = dr * s_nrm[0] * mi;
                    s_simw[n] = dw * s_nrm[1] * mi;
                }
            }
            __syncthreads();

            if (tid < 2) {
                const float* sims = tid ? s_simw : s_simr;
                float* wout = tid ? s_ws : s_wr;
                int*   iout = tid ? s_iw : s_ir;
                unsigned used = 0;
                float vals[4];
                #pragma unroll
                for (int k = 0; k < 4; k++) {
                    float best = -1e30f; int bi = 0;
                    for (int n = 0; n < MEMN; n++) {
                        if (!((used >> n) & 1u) && sims[n] > best) { best = sims[n]; bi = n; }
                    }
                    used |= 1u << bi;
                    iout[k] = bi; vals[k] = best;
                }
                float mx = vals[0], ssum = 0.f, e[4];
                #pragma unroll
                for (int k = 0; k < 4; k++) { e[k] = expf(vals[k] - mx); ssum += e[k]; }
                #pragma unroll
                for (int k = 0; k < 4; k++) wout[k] = e[k] / ssum;
            }
            __syncthreads();

            float r = 0.f;
            #pragma unroll
            for (int k = 0; k < 4; k++)
                r += s_wr[k] * g_M[(b*MEMN + s_ir[k])*KSZ + tid];
            g_r[b*KSZ + tid] = r;
            s_rnew[tid] = r;

            #pragma unroll
            for (int k = 0; k < 4; k++)
                g_M[(b*MEMN + s_iw[k])*KSZ + tid] += s_ws[k] * vv;

            if (t == TT - 1) {
                __syncthreads();
                if (wid < 4) {
                    const float* wrow = wo + wid*512;
                    float p = 0.f;
                    for (int j = lane; j < 256; j += 32) p += wrow[j]       * hnxt[b*HH + j];
                    for (int j = lane; j < 256; j += 32) p += wrow[256 + j] * s_rnew[j];
                    #pragma unroll
                    for (int o = 16; o > 0; o >>= 1) p += __shfl_xor_sync(0xffffffffu, p, o);
                    if (lane == 0) s_y[wid] = p + wob[wid];
                }
                __syncthreads();
                if (tid < 4 && (b*4 + tid) < out_size) out[b*4 + tid] = s_y[tid];
                if (tid == 0 && out_size >= BB*YY + BB) {
                    int am = 0; float bv = s_y[0];
                    #pragma unroll
                    for (int o = 1; o < 4; o++) if (s_y[o] > bv) { bv = s_y[o]; am = o; }
                    out[BB*YY + b] = (float)am;
                }
            }
        }
        if (t < TT - 1) { bt += NBLK; gridbar(bt); }
    }
}

// ---------------- launch ----------------
extern "C" void kernel_launch(void* const* d_in, const int* in_sizes, int n_in,
                              void* d_out, int out_size)
{
    const float* x    = (const float*)d_in[0];
    const float* c1w  = (const float*)d_in[1];
    const float* c1b  = (const float*)d_in[2];
    const float* c2w  = (const float*)d_in[3];
    const float* c2b  = (const float*)d_in[4];
    const float* c3w  = (const float*)d_in[5];
    const float* c3b  = (const float*)d_in[6];
    const float* fc1w = (const float*)d_in[7];
    const float* fc1b = (const float*)d_in[8];
    const float* fc2w = (const float*)d_in[9];
    const float* fc2b = (const float*)d_in[10];
    const float* gamma= (const float*)d_in[11];
    const float* beta = (const float*)d_in[12];
    const float* lwi  = (const float*)d_in[13];
    const float* lwh  = (const float*)d_in[14];
    const float* lb   = (const float*)d_in[15];
    const float* wk   = (const float*)d_in[16];
    const float* wwk  = (const float*)d_in[17];
    const float* wv   = (const float*)d_in[18];
    const float* wo   = (const float*)d_in[19];
    const float* wob  = (const float*)d_in[20];
    const float* mem0 = (const float*)d_in[21];
    float* out = (float*)d_out;

    cudaFuncSetAttribute(k_conv, cudaFuncAttributeMaxDynamicSharedMemorySize,
                         CONV_SMEM_FLOATS * 4);

    float *p_h3, *p_fc1, *p_z;
    cudaGetSymbolAddress((void**)&p_h3,  g_h3);
    cudaGetSymbolAddress((void**)&p_fc1, g_fc1);
    cudaGetSymbolAddress((void**)&p_z,   g_z);

    // setup: states, reordered weights, barrier reset, out zero
    k_setup<<<(BB*MEMN*KSZ + 255)/256, 256>>>(mem0, lwi, lwh, lb, wk, wwk, wv, out, out_size);

    // encoder
    k_conv<<<NFRM, 256, CONV_SMEM_FLOATS * 4>>>(x, c1w, c1b, c2w, c2b, c3w, c3b);
    k_gemm<<<dim3(4, 80), 256>>>(p_h3, 512, fc1w, 512, fc1b, p_fc1, 256, 512);
    k_gemm<<<dim3(2, 80), 256>>>(p_fc1, 256, fc2w, 256, fc2b, p_z, 128, 256);
    k_ctxnorm<<<BB, 128>>>(gamma, beta);

    // whole recurrence: one persistent launch
    k_scan<<<NBLK, 256>>>(wo, wob, out, out_size);
}

// round 4
// speedup vs baseline: 1.3803x; 1.3803x over previous
#include <cuda_runtime.h>
#include <math.h>

#define BB 256
#define TT 20
#define DD 128
#define HH 256
#define KSZ 256
#define MEMN 20
#define YY 4
#define EPSF 1e-8f
#define NFRM (BB*TT)

// ---------------- device scratch ----------------
__device__ float g_h3[NFRM*512];
__device__ float g_fc1[NFRM*256];
__device__ float g_fc2p[2*NFRM*DD];     // fc2 split-K partials
__device__ float g_z[NFRM*DD];
__device__ float g_gz[NFRM*1024];       // precomputed z@Wz^T + b
__device__ float g_gates4[4*BB*1024];   // gates split-K partials
__device__ float g_hpart[4*BB*768];     // heads split-K partials
__device__ float g_hst[BB*HH];
__device__ float g_cst[BB*HH];
__device__ float g_r[BB*KSZ];
__device__ float g_M[BB*MEMN*KSZ];
__device__ float g_Wcat[1024*512];      // [Wr | Wh]
__device__ float g_Wz[1024*128];
__device__ float g_Whead[768*256];

__device__ __forceinline__ float sigmf(float x){ return 1.f/(1.f+expf(-x)); }

// ---------------- fused conv encoder: one frame per block ----------------
#define S_IN 0
#define S_H1 1156
#define S_H2 12676
#define CONV_SMEM_FLOATS 16516

__global__ void __launch_bounds__(256, 3) k_conv(
    const float* __restrict__ x,
    const float* __restrict__ w1, const float* __restrict__ b1,
    const float* __restrict__ w2, const float* __restrict__ b2,
    const float* __restrict__ w3, const float* __restrict__ b3)
{
    extern __shared__ float sm[];
    float* s_in = sm + S_IN;
    float* s_h1 = sm + S_H1;
    float* s_h2 = sm + S_H2;
    const int f   = blockIdx.x;
    const int tid = threadIdx.x;

    for (int i = tid; i < CONV_SMEM_FLOATS; i += 256) sm[i] = 0.f;
    __syncthreads();
    for (int i = tid; i < 1024; i += 256) {
        int iy = i >> 5, ix = i & 31;
        s_in[(iy+1)*34 + ix + 1] = x[f*1024 + i];
    }
    __syncthreads();

    // ---- conv1: 1->32ch, 32x32 -> 16x16 ----
    for (int p = tid; p < 32*16; p += 256) {
        int oc = p >> 4, oy = p & 15;
        float bias = __ldg(b1 + oc);
        float acc[16];
        #pragma unroll
        for (int ox = 0; ox < 16; ox++) acc[ox] = bias;
        #pragma unroll
        for (int kh = 0; kh < 4; kh++) {
            const float* row = s_in + (2*oy+kh)*34;
            const float4 w = __ldg((const float4*)(w1 + oc*16 + kh*4));
            #pragma unroll
            for (int ox = 0; ox < 16; ox++) {
                acc[ox] += row[2*ox]*w.x + row[2*ox+1]*w.y
                         + row[2*ox+2]*w.z + row[2*ox+3]*w.w;
            }
        }
        float* dst = s_h1 + oc*360 + (oy+1)*20 + 1;
        #pragma unroll
        for (int ox = 0; ox < 16; ox++) dst[ox] = fmaxf(acc[ox], 0.f);
    }
    __syncthreads();

    // ---- conv2: 32->32ch, 16x16 -> 8x8; 128 threads, thread = (oc pair, oy),
    // ---- activation row loaded once, reused for both oc -> half LDS traffic
    if (tid < 128) {
        int ocp = tid >> 3;          // 0..15
        int oy  = tid & 7;           // 0..7
        int oc0 = ocp*2, oc1 = oc0 + 1;
        float bv0 = __ldg(b2 + oc0), bv1 = __ldg(b2 + oc1);
        float acc0[8] = {bv0,bv0,bv0,bv0,bv0,bv0,bv0,bv0};
        float acc1[8] = {bv1,bv1,bv1,bv1,bv1,bv1,bv1,bv1};
        for (int ic = 0; ic < 32; ic++) {
            const float* chan = s_h1 + ic*360;
            #pragma unroll
            for (int kh = 0; kh < 4; kh++) {
                const float* row = chan + (2*oy+kh)*20;
                float4 r0 = *(const float4*)(row);
                float4 r1 = *(const float4*)(row+4);
                float4 r2 = *(const float4*)(row+8);
                float4 r3 = *(const float4*)(row+12);
                float2 r4 = *(const float2*)(row+16);
                float rr[18] = {r0.x,r0.y,r0.z,r0.w, r1.x,r1.y,r1.z,r1.w,
                                r2.x,r2.y,r2.z,r2.w, r3.x,r3.y,r3.z,r3.w,
                                r4.x,r4.y};
                const float4 wa = __ldg((const float4*)(w2 + oc0*512 + ic*16 + kh*4));
                const float4 wb = __ldg((const float4*)(w2 + oc1*512 + ic*16 + kh*4));
                #pragma unroll
                for (int ox = 0; ox < 8; ox++) {
                    acc0[ox] += rr[2*ox]*wa.x + rr[2*ox+1]*wa.y
                              + rr[2*ox+2]*wa.z + rr[2*ox+3]*wa.w;
                    acc1[ox] += rr[2*ox]*wb.x + rr[2*ox+1]*wb.y
                              + rr[2*ox+2]*wb.z + rr[2*ox+3]*wb.w;
                }
            }
        }
        float* d0 = s_h2 + oc0*120 + (oy+1)*12 + 1;
        float* d1 = s_h2 + oc1*120 + (oy+1)*12 + 1;
        #pragma unroll
        for (int ox = 0; ox < 8; ox++) {
            d0[ox] = fmaxf(acc0[ox], 0.f);
            d1[ox] = fmaxf(acc1[ox], 0.f);
        }
    }
    __syncthreads();

    // ---- conv3: 32->32ch, 8x8 -> 4x4 ----
    {
        int oc = tid >> 3, oy = (tid >> 1) & 3, q = tid & 1;
        float bias = __ldg(b3 + oc);
        float acc0 = bias, acc1 = bias;
        for (int ic = 0; ic < 32; ic++) {
            const float* chan = s_h2 + ic*120;
            #pragma unroll
            for (int kh = 0; kh < 4; kh++) {
                const float* row = chan + (2*oy+kh)*12 + 4*q;
                float4 a = *(const float4*)(row);
                float4 b = *(const float4*)(row+4);
                const float4 w = __ldg((const float4*)(w3 + oc*512 + ic*16 + kh*4));
                acc0 += a.x*w.x + a.y*w.y + a.z*w.z + a.w*w.w;
                acc1 += a.z*w.x + a.w*w.y + b.x*w.z + b.y*w.w;
            }
        }
        int base = f*512 + oc*16 + oy*4 + 2*q;
        g_h3[base]   = fmaxf(acc0, 0.f);
        g_h3[base+1] = fmaxf(acc1, 0.f);
    }
}

// ---------------- full-K GEMM: C = act(A @ W^T + bias), 64x64 tiles ----------------
__global__ void __launch_bounds__(256) k_gemm(
    const float* __restrict__ A, int lda,
    const float* __restrict__ W, int ldw,
    const float* __restrict__ bias,
    float* __restrict__ C, int ldc, int K, int act)
{
    __shared__ float sA[2][16][68];
    __shared__ float sW[2][16][68];
    int tid = threadIdx.x;
    int tx = tid & 15, ty = tid >> 4;
    int lr = tid >> 2;
    int lk = (tid & 3) << 2;
    const float* Ab = A + (blockIdx.y*64 + lr)*lda + lk;
    const float* Wb = W + (blockIdx.x*64 + lr)*ldw + lk;

    float acc[4][4];
    #pragma unroll
    for (int i = 0; i < 4; i++)
        #pragma unroll
        for (int j = 0; j < 4; j++) acc[i][j] = 0.f;

    int nk = K >> 4;
    float4 a4 = *(const float4*)(Ab);
    float4 w4 = *(const float4*)(Wb);
    sA[0][lk+0][lr] = a4.x; sA[0][lk+1][lr] = a4.y; sA[0][lk+2][lr] = a4.z; sA[0][lk+3][lr] = a4.w;
    sW[0][lk+0][lr] = w4.x; sW[0][lk+1][lr] = w4.y; sW[0][lk+2][lr] = w4.z; sW[0][lk+3][lr] = w4.w;
    __syncthreads();

    for (int kb = 0; kb < nk; kb++) {
        int s = kb & 1;
        float4 na, nw;
        if (kb + 1 < nk) {
            na = *(const float4*)(Ab + ((kb+1) << 4));
            nw = *(const float4*)(Wb + ((kb+1) << 4));
        }
        #pragma unroll
        for (int kk = 0; kk < 16; kk++) {
            float4 av = *(const float4*)&sA[s][kk][ty<<2];
            float4 wv = *(const float4*)&sW[s][kk][tx<<2];
            float a[4] = {av.x, av.y, av.z, av.w};
            float w[4] = {wv.x, wv.y, wv.z, wv.w};
            #pragma unroll
            for (int i = 0; i < 4; i++)
                #pragma unroll
                for (int j = 0; j < 4; j++) acc[i][j] += a[i]*w[j];
        }
        if (kb + 1 < nk) {
            int d = s ^ 1;
            sA[d][lk+0][lr] = na.x; sA[d][lk+1][lr] = na.y; sA[d][lk+2][lr] = na.z; sA[d][lk+3][lr] = na.w;
            sW[d][lk+0][lr] = nw.x; sW[d][lk+1][lr] = nw.y; sW[d][lk+2][lr] = nw.z; sW[d][lk+3][lr] = nw.w;
            __syncthreads();
        }
    }
    int rb = blockIdx.y*64 + (ty<<2);
    int cb = blockIdx.x*64 + (tx<<2);
    #pragma unroll
    for (int i = 0; i < 4; i++)
        #pragma unroll
        for (int j = 0; j < 4; j++) {
            float v = acc[i][j] + bias[cb+j];
            if (act == 1) v = fmaxf(v, 0.f);
            C[(rb+i)*ldc + cb + j] = v;
        }
}

// ---------------- split-K partial GEMM: Cpart[z] = A[:,zKs:(z+1)Ks] @ W^T slice --------
// mode 0: plain A (lda). mode 1: A row b = [r(b,:), h(b,:)] gather (512 cols).
__global__ void __launch_bounds__(256) k_gemm_part(
    const float* __restrict__ A, int lda,
    const float* __restrict__ W, int ldw,
    float* __restrict__ C, int ldc,
    int Ksplit, int partStride, int mode)
{
    __shared__ float sA[2][16][68];
    __shared__ float sW[2][16][68];
    int tid = threadIdx.x;
    int tx = tid & 15, ty = tid >> 4;
    int lr = tid >> 2;
    int lk = (tid & 3) << 2;
    int z = blockIdx.z;
    int kStart = z * Ksplit;
    int rowA = blockIdx.y*64 + lr;
    const float* Wb = W + (blockIdx.x*64 + lr)*ldw + kStart + lk;
    float* Cp = C + z * partStride;

    auto ldA = [&](int k0) -> float4 {
        int c = kStart + k0 + lk;
        if (mode == 0) return *(const float4*)(A + rowA*lda + c);
        if (c < KSZ)   return *(const float4*)(g_r + rowA*KSZ + c);
        return *(const float4*)(g_hst + rowA*HH + (c - KSZ));
    };

    float acc[4][4];
    #pragma unroll
    for (int i = 0; i < 4; i++)
        #pragma unroll
        for (int j = 0; j < 4; j++) acc[i][j] = 0.f;

    int nk = Ksplit >> 4;
    float4 a4 = ldA(0);
    float4 w4 = *(const float4*)(Wb);
    sA[0][lk+0][lr] = a4.x; sA[0][lk+1][lr] = a4.y; sA[0][lk+2][lr] = a4.z; sA[0][lk+3][lr] = a4.w;
    sW[0][lk+0][lr] = w4.x; sW[0][lk+1][lr] = w4.y; sW[0][lk+2][lr] = w4.z; sW[0][lk+3][lr] = w4.w;
    __syncthreads();

    for (int kb = 0; kb < nk; kb++) {
        int s = kb & 1;
        float4 na, nw;
        if (kb + 1 < nk) {
            na = ldA((kb+1) << 4);
            nw = *(const float4*)(Wb + ((kb+1) << 4));
        }
        #pragma unroll
        for (int kk = 0; kk < 16; kk++) {
            float4 av = *(const float4*)&sA[s][kk][ty<<2];
            float4 wv = *(const float4*)&sW[s][kk][tx<<2];
            float a[4] = {av.x, av.y, av.z, av.w};
            float w[4] = {wv.x, wv.y, wv.z, wv.w};
            #pragma unroll
            for (int i = 0; i < 4; i++)
                #pragma unroll
                for (int j = 0; j < 4; j++) acc[i][j] += a[i]*w[j];
        }
        if (kb + 1 < nk) {
            int d = s ^ 1;
            sA[d][lk+0][lr] = na.x; sA[d][lk+1][lr] = na.y; sA[d][lk+2][lr] = na.z; sA[d][lk+3][lr] = na.w;
            sW[d][lk+0][lr] = nw.x; sW[d][lk+1][lr] = nw.y; sW[d][lk+2][lr] = nw.z; sW[d][lk+3][lr] = nw.w;
            __syncthreads();
        }
    }
    int rb = blockIdx.y*64 + (ty<<2);
    int cb = blockIdx.x*64 + (tx<<2);
    #pragma unroll
    for (int i = 0; i < 4; i++)
        #pragma unroll
        for (int j = 0; j < 4; j++)
            Cp[(rb+i)*ldc + cb + j] = acc[i][j];
}

// ---------------- context norm over time, fused fc2 combine + bias + relu ------------
__global__ void k_ctxnorm(const float* __restrict__ fc2b,
                          const float* __restrict__ gamma, const float* __restrict__ beta)
{
    int b = blockIdx.x, d = threadIdx.x;
    float bias = fc2b[d];
    float v[TT];
    float s = 0.f, s2 = 0.f;
    #pragma unroll
    for (int t = 0; t < TT; t++) {
        int idx = (b*TT+t)*DD + d;
        v[t] = fmaxf(g_fc2p[idx] + g_fc2p[NFRM*DD + idx] + bias, 0.f);
        s += v[t]; s2 += v[t]*v[t];
    }
    float mu  = s / TT;
    float var = (s2 - TT*mu*mu) / (TT - 1);
    float inv = 1.f / sqrtf(var + EPSF);
    float ga = gamma[d], be = beta[d];
    #pragma unroll
    for (int t = 0; t < TT; t++)
        g_z[(b*TT+t)*DD + d] = (v[t] - mu)*inv*ga + be;
}

// ---------------- setup ----------------
__global__ void k_setup(const float* __restrict__ mem0,
                        const float* __restrict__ wi, const float* __restrict__ wh,
                        const float* __restrict__ wk, const float* __restrict__ wwk,
                        const float* __restrict__ wv,
                        float* __restrict__ out, int out_size)
{
    int i = blockIdx.x*256 + threadIdx.x;
    if (i < BB*MEMN*KSZ) g_M[i] = mem0[i % (MEMN*KSZ)];
    if (i < 1024*512) {
        int j = i >> 9, c = i & 511;
        g_Wcat[i] = (c < 256) ? wi[j*384 + 128 + c] : wh[j*256 + (c-256)];
    }
    if (i < 1024*128) {
        int j = i >> 7, c = i & 127;
        g_Wz[i] = wi[j*384 + c];
    }
    if (i < 768*256) {
        int n = i >> 8;
        g_Whead[i] = (n < 256) ? wk[i] : ((n < 512) ? wwk[i - 256*256] : wv[i - 512*256]);
    }
    if (i < BB*HH) { g_hst[i] = 0.f; g_cst[i] = 0.f; }
    if (i < BB*KSZ) g_r[i] = 0.f;
    if (i < out_size) out[i] = 0.f;
}

// ---------------- per-step: LSTM update (sums gz + 4 gate partials) ----------------
__global__ void k_lstm(int t)
{
    int i = blockIdx.x*256 + threadIdx.x;   // BB*HH
    int b = i >> 8, j = i & 255;
    const float* gz = g_gz + (b*TT + t)*1024;
    int base = b*1024;
    float g4[4];
    #pragma unroll
    for (int gt = 0; gt < 4; gt++) {
        int col = gt*256 + j;
        float v = gz[col];
        #pragma unroll
        for (int z = 0; z < 4; z++) v += g_gates4[z*(BB*1024) + base + col];
        g4[gt] = v;
    }
    float c = sigmf(g4[1])*g_cst[i] + sigmf(g4[0])*tanhf(g4[2]);
    float h = sigmf(g4[3])*tanhf(c);
    g_cst[i] = c;
    g_hst[i] = h;
}

// ---------------- per-step: memory read/write + (last step) output ----------------
__global__ void __launch_bounds__(256) k_mem(int t, const float* __restrict__ wo,
                                             const float* __restrict__ wob,
                                             float* __restrict__ out, int out_size)
{
    __shared__ float s_kr[256], s_kw[256], s_rnew[256];
    __shared__ float s_simr[MEMN], s_simw[MEMN];
    __shared__ float s_wr[4], s_ws[4];
    __shared__ int   s_ir[4], s_iw[4];
    __shared__ float s_red[16];
    __shared__ float s_nrm[2];
    __shared__ float s_y[4];

    int b = blockIdx.x, tid = threadIdx.x;
    int lane = tid & 31, wid = tid >> 5;

    float kr = 0.f, kw = 0.f, vvs = 0.f;
    #pragma unroll
    for (int z = 0; z < 4; z++) {
        const float* hp = g_hpart + z*(BB*768) + b*768;
        kr  += hp[tid];
        kw  += hp[256 + tid];
        vvs += hp[512 + tid];
    }
    float vv = tanhf(vvs);
    s_kr[tid] = kr;
    s_kw[tid] = kw;

    float pr = kr*kr, pw = kw*kw;
    #pragma unroll
    for (int o = 16; o > 0; o >>= 1) {
        pr += __shfl_xor_sync(0xffffffffu, pr, o);
        pw += __shfl_xor_sync(0xffffffffu, pw, o);
    }
    if (lane == 0) { s_red[wid] = pr; s_red[8 + wid] = pw; }
    __syncthreads();
    if (tid == 0) {
        float sr = 0.f, sw = 0.f;
        #pragma unroll
        for (int w = 0; w < 8; w++) { sr += s_red[w]; sw += s_red[8 + w]; }
        s_nrm[0] = 1.f / (sqrtf(sr) + EPSF);
        s_nrm[1] = 1.f / (sqrtf(sw) + EPSF);
    }
    __syncthreads();

    for (int n = wid; n < MEMN; n += 8) {
        const float* Mr = g_M + (b*MEMN + n)*KSZ;
        float dr = 0.f, dw = 0.f, nn = 0.f;
        #pragma unroll
        for (int d0 = 0; d0 < KSZ; d0 += 32) {
            float m = Mr[d0 + lane];
            dr += s_kr[d0 + lane]*m;
            dw += s_kw[d0 + lane]*m;
            nn += m*m;
        }
        #pragma unroll
        for (int o = 16; o > 0; o >>= 1) {
            dr += __shfl_xor_sync(0xffffffffu, dr, o);
            dw += __shfl_xor_sync(0xffffffffu, dw, o);
            nn += __shfl_xor_sync(0xffffffffu, nn, o);
        }
        if (lane == 0) {
            float mi = 1.f / (sqrtf(nn) + EPSF);
            s_simr[n] = dr * s_nrm[0] * mi;
            s_simw[n] = dw * s_nrm[1] * mi;
        }
    }
    __syncthreads();

    if (tid < 2) {
        const float* sims = tid ? s_simw : s_simr;
        float* wout = tid ? s_ws : s_wr;
        int*   iout = tid ? s_iw : s_ir;
        unsigned used = 0;
        float vals[4];
        #pragma unroll
        for (int k = 0; k < 4; k++) {
            float best = -1e30f; int bi = 0;
            for (int n = 0; n < MEMN; n++) {
                if (!((used >> n) & 1u) && sims[n] > best) { best = sims[n]; bi = n; }
            }
            used |= 1u << bi;
            iout[k] = bi; vals[k] = best;
        }
        float mx = vals[0], ssum = 0.f, e[4];
        #pragma unroll
        for (int k = 0; k < 4; k++) { e[k] = expf(vals[k] - mx); ssum += e[k]; }
        #pragma unroll
        for (int k = 0; k < 4; k++) wout[k] = e[k] / ssum;
    }
    __syncthreads();

    float r = 0.f;
    #pragma unroll
    for (int k = 0; k < 4; k++)
        r += s_wr[k] * g_M[(b*MEMN + s_ir[k])*KSZ + tid];
    g_r[b*KSZ + tid] = r;
    s_rnew[tid] = r;

    #pragma unroll
    for (int k = 0; k < 4; k++)
        g_M[(b*MEMN + s_iw[k])*KSZ + tid] += s_ws[k] * vv;

    if (t == TT - 1) {
        __syncthreads();
        if (wid < 4) {
            const float* wrow = wo + wid*512;
            float p = 0.f;
            for (int j = lane; j < 256; j += 32) p += wrow[j]       * g_hst[b*HH + j];
            for (int j = lane; j < 256; j += 32) p += wrow[256 + j] * s_rnew[j];
            #pragma unroll
            for (int o = 16; o > 0; o >>= 1) p += __shfl_xor_sync(0xffffffffu, p, o);
            if (lane == 0) s_y[wid] = p + wob[wid];
        }
        __syncthreads();
        if (tid < 4 && (b*4 + tid) < out_size) out[b*4 + tid] = s_y[tid];
        if (tid == 0 && out_size >= BB*YY + BB) {
            int am = 0; float bv = s_y[0];
            #pragma unroll
            for (int o = 1; o < 4; o++) if (s_y[o] > bv) { bv = s_y[o]; am = o; }
            out[BB*YY + b] = (float)am;
        }
    }
}

// ---------------- launch ----------------
extern "C" void kernel_launch(void* const* d_in, const int* in_sizes, int n_in,
                              void* d_out, int out_size)
{
    const float* x    = (const float*)d_in[0];
    const float* c1w  = (const float*)d_in[1];
    const float* c1b  = (const float*)d_in[2];
    const float* c2w  = (const float*)d_in[3];
    const float* c2b  = (const float*)d_in[4];
    const float* c3w  = (const float*)d_in[5];
    const float* c3b  = (const float*)d_in[6];
    const float* fc1w = (const float*)d_in[7];
    const float* fc1b = (const float*)d_in[8];
    const float* fc2w = (const float*)d_in[9];
    const float* fc2b = (const float*)d_in[10];
    const float* gamma= (const float*)d_in[11];
    const float* beta = (const float*)d_in[12];
    const float* lwi  = (const float*)d_in[13];
    const float* lwh  = (const float*)d_in[14];
    const float* lb   = (const float*)d_in[15];
    const float* wk   = (const float*)d_in[16];
    const float* wwk  = (const float*)d_in[17];
    const float* wv   = (const float*)d_in[18];
    const float* wo   = (const float*)d_in[19];
    const float* wob  = (const float*)d_in[20];
    const float* mem0 = (const float*)d_in[21];
    float* out = (float*)d_out;

    cudaFuncSetAttribute(k_conv, cudaFuncAttributeMaxDynamicSharedMemorySize,
                         CONV_SMEM_FLOATS * 4);

    float *p_h3, *p_fc1, *p_fc2p, *p_z, *p_gz, *p_g4, *p_hp, *p_h, *p_wcat, *p_wz, *p_whead;
    cudaGetSymbolAddress((void**)&p_h3,    g_h3);
    cudaGetSymbolAddress((void**)&p_fc1,   g_fc1);
    cudaGetSymbolAddress((void**)&p_fc2p,  g_fc2p);
    cudaGetSymbolAddress((void**)&p_z,     g_z);
    cudaGetSymbolAddress((void**)&p_gz,    g_gz);
    cudaGetSymbolAddress((void**)&p_g4,    g_gates4);
    cudaGetSymbolAddress((void**)&p_hp,    g_hpart);
    cudaGetSymbolAddress((void**)&p_h,     g_hst);
    cudaGetSymbolAddress((void**)&p_wcat,  g_Wcat);
    cudaGetSymbolAddress((void**)&p_wz,    g_Wz);
    cudaGetSymbolAddress((void**)&p_whead, g_Whead);

    k_setup<<<(BB*MEMN*KSZ + 255)/256, 256>>>(mem0, lwi, lwh, wk, wwk, wv, out, out_size);

    // encoder
    k_conv<<<NFRM, 256, CONV_SMEM_FLOATS * 4>>>(x, c1w, c1b, c2w, c2b, c3w, c3b);
    // fc1: [5120,512]@[256,512]^T -> relu (320 blocks)
    k_gemm<<<dim3(4, 80), 256>>>(p_h3, 512, fc1w, 512, fc1b, p_fc1, 256, 512, 1);
    // fc2: split-K x2 partials (320 blocks); combine in ctxnorm
    k_gemm_part<<<dim3(2, 80, 2), 256>>>(p_fc1, 256, fc2w, 256, p_fc2p, 128,
                                         128, NFRM*DD, 0);
    k_ctxnorm<<<BB, 128>>>(fc2b, gamma, beta);
    // Gz = z @ Wz^T + lstm_b for all (b,t): [5120,128]@[1024,128]^T (1280 blocks)
    k_gemm<<<dim3(16, 80), 256>>>(p_z, 128, p_wz, 128, lb, p_gz, 1024, 128, 0);

    for (int t = 0; t < TT; t++) {
        // gates: [r|h] @ Wcat^T, split-K x4 (256 blocks)
        k_gemm_part<<<dim3(16, 4, 4), 256>>>(nullptr, 0, p_wcat, 512, p_g4, 1024,
                                             128, BB*1024, 1);
        k_lstm<<<BB*HH/256, 256>>>(t);
        // heads: h @ Whead^T, split-K x4 (192 blocks)
        k_gemm_part<<<dim3(12, 4, 4), 256>>>(p_h, 256, p_whead, 256, p_hp, 768,
                                             64, BB*768, 0);
        k_mem<<<BB, 256>>>(t, wo, wob, out, out_size);
    }
}